// round 3
// baseline (speedup 1.0000x reference)
#include <cuda_runtime.h>
#include <cuda_bf16.h>
#include <cstdint>
#include <cstddef>

// ---------------- helpers ----------------
__device__ __forceinline__ uint32_t smem_u32(const void* p) {
    uint32_t a;
    asm("{ .reg .u64 t; cvta.to.shared.u64 t, %1; cvt.u32.u64 %0, t; }" : "=r"(a) : "l"(p));
    return a;
}
__device__ __forceinline__ void ldm_x4(uint32_t* r, uint32_t addr) {
    asm volatile("ldmatrix.sync.aligned.m8n8.x4.shared.b16 {%0,%1,%2,%3}, [%4];"
                 : "=r"(r[0]), "=r"(r[1]), "=r"(r[2]), "=r"(r[3]) : "r"(addr));
}
__device__ __forceinline__ void mma_bf16(float* c, const uint32_t* a, const uint32_t* b) {
    asm volatile("mma.sync.aligned.m16n8k16.row.col.f32.bf16.bf16.f32 "
                 "{%0,%1,%2,%3}, {%4,%5,%6,%7}, {%8,%9}, {%0,%1,%2,%3};"
                 : "+f"(c[0]), "+f"(c[1]), "+f"(c[2]), "+f"(c[3])
                 : "r"(a[0]), "r"(a[1]), "r"(a[2]), "r"(a[3]), "r"(b[0]), "r"(b[1]));
}
#define CP_ASYNC16(dst, src) \
    asm volatile("cp.async.cg.shared.global [%0], [%1], 16;" :: "r"(dst), "l"(src))
#define CP_COMMIT() asm volatile("cp.async.commit_group;" ::: "memory")

// ---------------- problem constants ----------------
#define NE 8388608            // 4*2048*1024
#define NS 16777216           // 4*2048*2048
#define WN 1048576            // 1024*1024

static constexpr int BK = 32;
static constexpr int SST = 40;                 // smem row stride (bf16): 80B, conflict-free
static constexpr int MATB = 128 * SST * 2;     // 10240 B per tile
static constexpr int STAGEB = 4 * MATB;        // 40960 B per stage
static constexpr unsigned SMEM_BYTES = 2 * STAGEB;  // 81920

// ---------------- scratch (device globals) ----------------
__device__ __align__(256) __nv_bfloat16 g_xh[3ull * NE];
__device__ __align__(256) __nv_bfloat16 g_xl[3ull * NE];
__device__ __align__(256) __nv_bfloat16 g_wh[3ull * WN];
__device__ __align__(256) __nv_bfloat16 g_wl[3ull * WN];
__device__ __align__(256) __nv_bfloat16 g_qh[3ull * NE];
__device__ __align__(256) __nv_bfloat16 g_ql[3ull * NE];
__device__ __align__(256) __nv_bfloat16 g_vth[NE];
__device__ __align__(256) __nv_bfloat16 g_vtl[NE];
__device__ __align__(256) float         g_S[NS];
__device__ __align__(256) __nv_bfloat16 g_ph[NS];
__device__ __align__(256) __nv_bfloat16 g_pl[NS];

// ---------------- elementwise kernels ----------------
__global__ void split_f32(const float* __restrict__ in, __nv_bfloat16* __restrict__ hi,
                          __nv_bfloat16* __restrict__ lo, int n) {
    int i = (blockIdx.x * blockDim.x + threadIdx.x) * 4;
    if (i >= n) return;
    float4 v = *reinterpret_cast<const float4*>(in + i);
    float f[4] = {v.x, v.y, v.z, v.w};
    __nv_bfloat16 h[4], l[4];
#pragma unroll
    for (int j = 0; j < 4; j++) {
        h[j] = __float2bfloat16(f[j]);
        l[j] = __float2bfloat16(f[j] - __bfloat162float(h[j]));
    }
    reinterpret_cast<__nv_bfloat162*>(hi + i)[0] = __halves2bfloat162(h[0], h[1]);
    reinterpret_cast<__nv_bfloat162*>(hi + i)[1] = __halves2bfloat162(h[2], h[3]);
    reinterpret_cast<__nv_bfloat162*>(lo + i)[0] = __halves2bfloat162(l[0], l[1]);
    reinterpret_cast<__nv_bfloat162*>(lo + i)[1] = __halves2bfloat162(l[2], l[3]);
}

// W[d][n] f32 -> Wt hi/lo [n][d] bf16
__global__ void wsplit_t(const float* __restrict__ W, __nv_bfloat16* __restrict__ oh,
                         __nv_bfloat16* __restrict__ ol) {
    __shared__ float t[32][33];
    int n0 = blockIdx.x * 32, k0 = blockIdx.y * 32;
    int tx = threadIdx.x, ty = threadIdx.y;
#pragma unroll
    for (int i = 0; i < 4; i++)
        t[ty + i * 8][tx] = W[(size_t)(k0 + ty + i * 8) * 1024 + n0 + tx];
    __syncthreads();
#pragma unroll
    for (int i = 0; i < 4; i++) {
        float v = t[tx][ty + i * 8];
        __nv_bfloat16 h = __float2bfloat16(v);
        __nv_bfloat16 l = __float2bfloat16(v - __bfloat162float(h));
        size_t o = (size_t)(n0 + ty + i * 8) * 1024 + k0 + tx;
        oh[o] = h; ol[o] = l;
    }
}

// V hi/lo [b][s][v] -> Vt hi/lo [b][v][s]
__global__ void vtrans(const __nv_bfloat16* __restrict__ vh, const __nv_bfloat16* __restrict__ vl,
                       __nv_bfloat16* __restrict__ oh, __nv_bfloat16* __restrict__ ol) {
    __shared__ __nv_bfloat16 th[32][33], tl[32][33];
    int b = blockIdx.z;
    size_t inOff = (size_t)b * 2048 * 1024, outOff = (size_t)b * 1024 * 2048;
    int v0 = blockIdx.x * 32, s0 = blockIdx.y * 32;
    int tx = threadIdx.x, ty = threadIdx.y;
#pragma unroll
    for (int i = 0; i < 4; i++) {
        size_t idx = inOff + (size_t)(s0 + ty + i * 8) * 1024 + v0 + tx;
        th[ty + i * 8][tx] = vh[idx];
        tl[ty + i * 8][tx] = vl[idx];
    }
    __syncthreads();
#pragma unroll
    for (int i = 0; i < 4; i++) {
        size_t o = outOff + (size_t)(v0 + ty + i * 8) * 2048 + s0 + tx;
        oh[o] = th[tx][ty + i * 8];
        ol[o] = tl[tx][ty + i * 8];
    }
}

// row softmax over 2048 -> split bf16 probs
__global__ void softmax_split(const float* __restrict__ S, __nv_bfloat16* __restrict__ ph,
                              __nv_bfloat16* __restrict__ pl) {
    const int row = blockIdx.x;
    const float* x = S + (size_t)row * 2048;
    const int tid = threadIdx.x;  // 256
    float v[8];
    float mx = -1e30f;
#pragma unroll
    for (int i = 0; i < 8; i++) { v[i] = x[tid + i * 256]; mx = fmaxf(mx, v[i]); }
#pragma unroll
    for (int o = 16; o; o >>= 1) mx = fmaxf(mx, __shfl_xor_sync(0xFFFFFFFFu, mx, o));
    __shared__ float redm[8], reds[8];
    if ((tid & 31) == 0) redm[tid >> 5] = mx;
    __syncthreads();
    float m2 = redm[0];
#pragma unroll
    for (int w = 1; w < 8; w++) m2 = fmaxf(m2, redm[w]);
    float s = 0.f;
#pragma unroll
    for (int i = 0; i < 8; i++) { v[i] = __expf(v[i] - m2); s += v[i]; }
#pragma unroll
    for (int o = 16; o; o >>= 1) s += __shfl_xor_sync(0xFFFFFFFFu, s, o);
    if ((tid & 31) == 0) reds[tid >> 5] = s;
    __syncthreads();
    float st = 0.f;
#pragma unroll
    for (int w = 0; w < 8; w++) st += reds[w];
    float inv = 1.f / st;
#pragma unroll
    for (int i = 0; i < 8; i++) {
        float p = v[i] * inv;
        __nv_bfloat16 h = __float2bfloat16(p);
        __nv_bfloat16 l = __float2bfloat16(p - __bfloat162float(h));
        size_t o = (size_t)row * 2048 + tid + i * 256;
        ph[o] = h; pl[o] = l;
    }
}

// ---------------- HMMA split-bf16 GEMM: C[128x128] per CTA ----------------
// A row-major [M][K] (lda=K), B K-major [N][K] (ldb=K). bf16x3: AhBh+AhBl+AlBh.
// MODE 0: out = split(val + bias[col]) -> outH/outL ; MODE 1: outF = val*scale.
template <int MODE>
__global__ void __launch_bounds__(256, 1)
gemm_bf16x3(const __nv_bfloat16* __restrict__ Ah, const __nv_bfloat16* __restrict__ Al,
            const __nv_bfloat16* __restrict__ Bh, const __nv_bfloat16* __restrict__ Bl,
            int lda, int ldb, int ldc, int K,
            size_t aBatch, size_t bBatch, size_t cBatch,
            const float* __restrict__ bias, float scale,
            float* __restrict__ outF, __nv_bfloat16* __restrict__ outH,
            __nv_bfloat16* __restrict__ outL) {
    extern __shared__ char sm[];
    const uint32_t sbase = smem_u32(sm);
    const int tid = threadIdx.x;
    const int lane = tid & 31, wid = tid >> 5;
    const int wm = wid >> 2, wn = wid & 3;  // 2 x 4 warp grid
    const int z = blockIdx.z;
    Ah += (size_t)z * aBatch; Al += (size_t)z * aBatch;
    Bh += (size_t)z * bBatch; Bl += (size_t)z * bBatch;
    if (MODE == 0) { outH += (size_t)z * cBatch; outL += (size_t)z * cBatch; }
    else           { outF += (size_t)z * cBatch; }

    const int mBase = blockIdx.y * 128;
    const int nBase = blockIdx.x * 128;
    const int KT = K / BK;

    // cp.async loader for one k-tile into stage
    auto issue_load = [&](int kb, int stage) {
        const int kOff = kb * BK;
        const uint32_t sb = sbase + stage * STAGEB;
#pragma unroll
        for (int mat = 0; mat < 4; mat++) {
            const __nv_bfloat16* g = (mat == 0) ? Ah : (mat == 1) ? Al : (mat == 2) ? Bh : Bl;
            const int ld = (mat < 2) ? lda : ldb;
            const int rb = (mat < 2) ? mBase : nBase;
#pragma unroll
            for (int i = 0; i < 2; i++) {
                int idx = tid + i * 256;          // 0..511
                int r = idx >> 2, c = idx & 3;    // 128 rows x 4 x 16B
                uint32_t daddr = sb + mat * MATB + (uint32_t)(r * SST + c * 8) * 2;
                const void* gp = g + (size_t)(rb + r) * ld + kOff + c * 8;
                CP_ASYNC16(daddr, gp);
            }
        }
        CP_COMMIT();
    };

    float acc[4][4][4];
#pragma unroll
    for (int i = 0; i < 4; i++)
#pragma unroll
        for (int j = 0; j < 4; j++)
#pragma unroll
            for (int e = 0; e < 4; e++) acc[i][j][e] = 0.f;

    issue_load(0, 0);

    for (int kb = 0; kb < KT; kb++) {
        if (kb + 1 < KT) {
            issue_load(kb + 1, (kb + 1) & 1);
            asm volatile("cp.async.wait_group 1;" ::: "memory");
        } else {
            asm volatile("cp.async.wait_group 0;" ::: "memory");
        }
        __syncthreads();

        const uint32_t sb = sbase + (kb & 1) * STAGEB;
#pragma unroll
        for (int ks = 0; ks < 2; ks++) {
            // A fragments (hi & lo): 4 m-tiles
            uint32_t ah[4][4], al[4][4];
            const int rowA = wm * 64 + (lane & 15);
            const int colA = ks * 16 + (lane >> 4) * 8;
#pragma unroll
            for (int mt = 0; mt < 4; mt++) {
                uint32_t off = (uint32_t)((rowA + mt * 16) * SST + colA) * 2;
                ldm_x4(ah[mt], sb + 0 * MATB + off);
                ldm_x4(al[mt], sb + 1 * MATB + off);
            }
            // B fragments (hi & lo): 4 n-tiles via 2 x ldmatrix.x4
            uint32_t bh[4][2], bl[4][2];
            const int rB = wn * 32 + ((lane >> 4) << 3) + (lane & 7);
            const int cB = ks * 16 + (((lane >> 3) & 1) << 3);
#pragma unroll
            for (int bp = 0; bp < 2; bp++) {
                uint32_t off = (uint32_t)((rB + bp * 16) * SST + cB) * 2;
                uint32_t th[4], tl[4];
                ldm_x4(th, sb + 2 * MATB + off);
                ldm_x4(tl, sb + 3 * MATB + off);
                bh[bp * 2][0] = th[0]; bh[bp * 2][1] = th[1];
                bh[bp * 2 + 1][0] = th[2]; bh[bp * 2 + 1][1] = th[3];
                bl[bp * 2][0] = tl[0]; bl[bp * 2][1] = tl[1];
                bl[bp * 2 + 1][0] = tl[2]; bl[bp * 2 + 1][1] = tl[3];
            }
#pragma unroll
            for (int mt = 0; mt < 4; mt++)
#pragma unroll
                for (int nt = 0; nt < 4; nt++) {
                    mma_bf16(acc[mt][nt], ah[mt], bh[nt]);
                    mma_bf16(acc[mt][nt], ah[mt], bl[nt]);
                    mma_bf16(acc[mt][nt], al[mt], bh[nt]);
                }
        }
        __syncthreads();
    }

    // epilogue
    const int g = lane >> 2, tq = lane & 3;
#pragma unroll
    for (int mt = 0; mt < 4; mt++) {
        const int row = mBase + wm * 64 + mt * 16 + g;
#pragma unroll
        for (int nt = 0; nt < 4; nt++) {
            const int col = nBase + wn * 32 + nt * 8 + tq * 2;
            const float* c = acc[mt][nt];
            if (MODE == 0) {
                float b0 = bias[col], b1 = bias[col + 1];
#pragma unroll
                for (int e = 0; e < 4; e++) {
                    int rr = row + (e >> 1) * 8;
                    int cc = col + (e & 1);
                    float v = c[e] + ((e & 1) ? b1 : b0);
                    __nv_bfloat16 h = __float2bfloat16(v);
                    __nv_bfloat16 l = __float2bfloat16(v - __bfloat162float(h));
                    size_t o = (size_t)rr * ldc + cc;
                    outH[o] = h; outL[o] = l;
                }
            } else {
                float2 v0 = {c[0] * scale, c[1] * scale};
                float2 v1 = {c[2] * scale, c[3] * scale};
                *reinterpret_cast<float2*>(outF + (size_t)row * ldc + col) = v0;
                *reinterpret_cast<float2*>(outF + (size_t)(row + 8) * ldc + col) = v1;
            }
        }
    }
}

// ---------------- launch ----------------
extern "C" void kernel_launch(void* const* d_in, const int* in_sizes, int n_in,
                              void* d_out, int out_size) {
    const float* q_in = (const float*)d_in[0];
    const float* k_in = (const float*)d_in[1];
    const float* v_in = (const float*)d_in[2];
    const float* Wq   = (const float*)d_in[3];
    const float* bq   = (const float*)d_in[4];
    const float* Wk   = (const float*)d_in[5];
    const float* bk   = (const float*)d_in[6];
    const float* Wv   = (const float*)d_in[7];
    const float* bv   = (const float*)d_in[8];
    float* out = (float*)d_out;

    cudaFuncSetAttribute(gemm_bf16x3<0>, cudaFuncAttributeMaxDynamicSharedMemorySize, SMEM_BYTES);
    cudaFuncSetAttribute(gemm_bf16x3<1>, cudaFuncAttributeMaxDynamicSharedMemorySize, SMEM_BYTES);

    void* p;
    cudaGetSymbolAddress(&p, g_xh);  __nv_bfloat16* xh = (__nv_bfloat16*)p;
    cudaGetSymbolAddress(&p, g_xl);  __nv_bfloat16* xl = (__nv_bfloat16*)p;
    cudaGetSymbolAddress(&p, g_wh);  __nv_bfloat16* wh = (__nv_bfloat16*)p;
    cudaGetSymbolAddress(&p, g_wl);  __nv_bfloat16* wl = (__nv_bfloat16*)p;
    cudaGetSymbolAddress(&p, g_qh);  __nv_bfloat16* qh = (__nv_bfloat16*)p;
    cudaGetSymbolAddress(&p, g_ql);  __nv_bfloat16* ql = (__nv_bfloat16*)p;
    cudaGetSymbolAddress(&p, g_vth); __nv_bfloat16* vth = (__nv_bfloat16*)p;
    cudaGetSymbolAddress(&p, g_vtl); __nv_bfloat16* vtl = (__nv_bfloat16*)p;
    cudaGetSymbolAddress(&p, g_S);   float* Sb = (float*)p;
    cudaGetSymbolAddress(&p, g_ph);  __nv_bfloat16* ph = (__nv_bfloat16*)p;
    cudaGetSymbolAddress(&p, g_pl);  __nv_bfloat16* pl = (__nv_bfloat16*)p;

    const float* xin[3] = {q_in, k_in, v_in};
    const float* Ws[3]  = {Wq, Wk, Wv};
    const float* bs[3]  = {bq, bk, bv};

    for (int i = 0; i < 3; i++) {
        split_f32<<<NE / (256 * 4), 256>>>(xin[i], xh + (size_t)i * NE, xl + (size_t)i * NE, NE);
        wsplit_t<<<dim3(32, 32), dim3(32, 8)>>>(Ws[i], wh + (size_t)i * WN, wl + (size_t)i * WN);
    }
    // projections: [8192,1024] = X x W + b  -> split bf16
    for (int i = 0; i < 3; i++) {
        gemm_bf16x3<0><<<dim3(8, 64, 1), 256, SMEM_BYTES>>>(
            xh + (size_t)i * NE, xl + (size_t)i * NE, wh + (size_t)i * WN, wl + (size_t)i * WN,
            1024, 1024, 1024, 1024, 0, 0, 0,
            bs[i], 0.f, nullptr, qh + (size_t)i * NE, ql + (size_t)i * NE);
    }
    // scores: per batch S[2048,2048] = Q x K^T, scale 1/32
    gemm_bf16x3<1><<<dim3(16, 16, 4), 256, SMEM_BYTES>>>(
        qh, ql, qh + NE, ql + NE,
        1024, 1024, 2048, 1024,
        (size_t)2048 * 1024, (size_t)2048 * 1024, (size_t)2048 * 2048,
        nullptr, 0.03125f, Sb, nullptr, nullptr);
    softmax_split<<<8192, 256>>>(Sb, ph, pl);
    vtrans<<<dim3(32, 64, 4), dim3(32, 8)>>>(qh + 2ull * NE, ql + 2ull * NE, vth, vtl);
    // O = P x V  (B operand = V^T rows, K-major over s)
    gemm_bf16x3<1><<<dim3(8, 16, 4), 256, SMEM_BYTES>>>(
        ph, pl, vth, vtl,
        2048, 2048, 1024, 2048,
        (size_t)2048 * 2048, (size_t)1024 * 2048, (size_t)2048 * 1024,
        nullptr, 1.0f, out, nullptr, nullptr);
}

// round 4
// speedup vs baseline: 1.2225x; 1.2225x over previous
#include <cuda_runtime.h>
#include <cuda_bf16.h>
#include <cstdint>
#include <cstddef>

// ---------------- helpers ----------------
__device__ __forceinline__ uint32_t smem_u32(const void* p) {
    uint32_t a;
    asm("{ .reg .u64 t; cvta.to.shared.u64 t, %1; cvt.u32.u64 %0, t; }" : "=r"(a) : "l"(p));
    return a;
}
__device__ __forceinline__ void ldm_x4(uint32_t* r, uint32_t addr) {
    asm volatile("ldmatrix.sync.aligned.m8n8.x4.shared.b16 {%0,%1,%2,%3}, [%4];"
                 : "=r"(r[0]), "=r"(r[1]), "=r"(r[2]), "=r"(r[3]) : "r"(addr));
}
__device__ __forceinline__ void mma_bf16(float* c, const uint32_t* a, const uint32_t* b) {
    asm volatile("mma.sync.aligned.m16n8k16.row.col.f32.bf16.bf16.f32 "
                 "{%0,%1,%2,%3}, {%4,%5,%6,%7}, {%8,%9}, {%0,%1,%2,%3};"
                 : "+f"(c[0]), "+f"(c[1]), "+f"(c[2]), "+f"(c[3])
                 : "r"(a[0]), "r"(a[1]), "r"(a[2]), "r"(a[3]), "r"(b[0]), "r"(b[1]));
}
#define CP_ASYNC16(dst, src) \
    asm volatile("cp.async.cg.shared.global [%0], [%1], 16;" :: "r"(dst), "l"(src))
#define CP_COMMIT() asm volatile("cp.async.commit_group;" ::: "memory")

// ---------------- problem constants ----------------
#define NE 8388608            // 4*2048*1024
#define NS 16777216           // 4*2048*2048
#define WN 1048576            // 1024*1024

static constexpr int BK = 32;
static constexpr int SST = 40;                 // smem row stride (bf16): 80B, conflict-free
static constexpr int MATB = 128 * SST * 2;     // 10240 B per tile
static constexpr int STAGEB = 4 * MATB;        // 40960 B per stage
static constexpr unsigned SMEM_BYTES = 2 * STAGEB;  // 81920

// ---------------- scratch (device globals) ----------------
__device__ __align__(256) __nv_bfloat16 g_xh[3ull * NE];
__device__ __align__(256) __nv_bfloat16 g_xl[3ull * NE];
__device__ __align__(256) __nv_bfloat16 g_wh[3ull * WN];
__device__ __align__(256) __nv_bfloat16 g_wl[3ull * WN];
__device__ __align__(256) __nv_bfloat16 g_qh[3ull * NE];
__device__ __align__(256) __nv_bfloat16 g_ql[3ull * NE];
__device__ __align__(256) __nv_bfloat16 g_vth[NE];
__device__ __align__(256) __nv_bfloat16 g_vtl[NE];
__device__ __align__(256) float         g_S[NS];
__device__ __align__(256) __nv_bfloat16 g_ph[NS];
__device__ __align__(256) __nv_bfloat16 g_pl[NS];

// ---------------- elementwise kernels ----------------
__global__ void split_f32(const float* __restrict__ in, __nv_bfloat16* __restrict__ hi,
                          __nv_bfloat16* __restrict__ lo, int n) {
    int i = (blockIdx.x * blockDim.x + threadIdx.x) * 4;
    if (i >= n) return;
    float4 v = *reinterpret_cast<const float4*>(in + i);
    float f[4] = {v.x, v.y, v.z, v.w};
    __nv_bfloat16 h[4], l[4];
#pragma unroll
    for (int j = 0; j < 4; j++) {
        h[j] = __float2bfloat16(f[j]);
        l[j] = __float2bfloat16(f[j] - __bfloat162float(h[j]));
    }
    reinterpret_cast<__nv_bfloat162*>(hi + i)[0] = __halves2bfloat162(h[0], h[1]);
    reinterpret_cast<__nv_bfloat162*>(hi + i)[1] = __halves2bfloat162(h[2], h[3]);
    reinterpret_cast<__nv_bfloat162*>(lo + i)[0] = __halves2bfloat162(l[0], l[1]);
    reinterpret_cast<__nv_bfloat162*>(lo + i)[1] = __halves2bfloat162(l[2], l[3]);
}

// W[d][n] f32 -> Wt hi/lo [n][d] bf16
__global__ void wsplit_t(const float* __restrict__ W, __nv_bfloat16* __restrict__ oh,
                         __nv_bfloat16* __restrict__ ol) {
    __shared__ float t[32][33];
    int n0 = blockIdx.x * 32, k0 = blockIdx.y * 32;
    int tx = threadIdx.x, ty = threadIdx.y;
#pragma unroll
    for (int i = 0; i < 4; i++)
        t[ty + i * 8][tx] = W[(size_t)(k0 + ty + i * 8) * 1024 + n0 + tx];
    __syncthreads();
#pragma unroll
    for (int i = 0; i < 4; i++) {
        float v = t[tx][ty + i * 8];
        __nv_bfloat16 h = __float2bfloat16(v);
        __nv_bfloat16 l = __float2bfloat16(v - __bfloat162float(h));
        size_t o = (size_t)(n0 + ty + i * 8) * 1024 + k0 + tx;
        oh[o] = h; ol[o] = l;
    }
}

// V hi/lo [b][s][v] -> Vt hi/lo [b][v][s]
__global__ void vtrans(const __nv_bfloat16* __restrict__ vh, const __nv_bfloat16* __restrict__ vl,
                       __nv_bfloat16* __restrict__ oh, __nv_bfloat16* __restrict__ ol) {
    __shared__ __nv_bfloat16 th[32][33], tl[32][33];
    int b = blockIdx.z;
    size_t inOff = (size_t)b * 2048 * 1024, outOff = (size_t)b * 1024 * 2048;
    int v0 = blockIdx.x * 32, s0 = blockIdx.y * 32;
    int tx = threadIdx.x, ty = threadIdx.y;
#pragma unroll
    for (int i = 0; i < 4; i++) {
        size_t idx = inOff + (size_t)(s0 + ty + i * 8) * 1024 + v0 + tx;
        th[ty + i * 8][tx] = vh[idx];
        tl[ty + i * 8][tx] = vl[idx];
    }
    __syncthreads();
#pragma unroll
    for (int i = 0; i < 4; i++) {
        size_t o = outOff + (size_t)(v0 + ty + i * 8) * 2048 + s0 + tx;
        oh[o] = th[tx][ty + i * 8];
        ol[o] = tl[tx][ty + i * 8];
    }
}

// row softmax over 2048 -> split bf16 probs
__global__ void softmax_split(const float* __restrict__ S, __nv_bfloat16* __restrict__ ph,
                              __nv_bfloat16* __restrict__ pl) {
    const int row = blockIdx.x;
    const float* x = S + (size_t)row * 2048;
    const int tid = threadIdx.x;  // 256
    float v[8];
    float mx = -1e30f;
#pragma unroll
    for (int i = 0; i < 8; i++) { v[i] = x[tid + i * 256]; mx = fmaxf(mx, v[i]); }
#pragma unroll
    for (int o = 16; o; o >>= 1) mx = fmaxf(mx, __shfl_xor_sync(0xFFFFFFFFu, mx, o));
    __shared__ float redm[8], reds[8];
    if ((tid & 31) == 0) redm[tid >> 5] = mx;
    __syncthreads();
    float m2 = redm[0];
#pragma unroll
    for (int w = 1; w < 8; w++) m2 = fmaxf(m2, redm[w]);
    float s = 0.f;
#pragma unroll
    for (int i = 0; i < 8; i++) { v[i] = __expf(v[i] - m2); s += v[i]; }
#pragma unroll
    for (int o = 16; o; o >>= 1) s += __shfl_xor_sync(0xFFFFFFFFu, s, o);
    if ((tid & 31) == 0) reds[tid >> 5] = s;
    __syncthreads();
    float st = 0.f;
#pragma unroll
    for (int w = 0; w < 8; w++) st += reds[w];
    float inv = 1.f / st;
#pragma unroll
    for (int i = 0; i < 8; i++) {
        float p = v[i] * inv;
        __nv_bfloat16 h = __float2bfloat16(p);
        __nv_bfloat16 l = __float2bfloat16(p - __bfloat162float(h));
        size_t o = (size_t)row * 2048 + tid + i * 256;
        ph[o] = h; pl[o] = l;
    }
}

// ---------------- HMMA split-bf16 GEMM: C[128x128] per CTA ----------------
// A row-major [M][K] (lda=K), B K-major [N][K] (ldb=K). bf16x3: AhBh+AhBl+AlBh.
// MODE 0: out = split(val + bias[col]) -> outH/outL ; MODE 1: outF = val*scale.
template <int MODE>
__global__ void __launch_bounds__(256, 2)
gemm_bf16x3(const __nv_bfloat16* __restrict__ Ah, const __nv_bfloat16* __restrict__ Al,
            const __nv_bfloat16* __restrict__ Bh, const __nv_bfloat16* __restrict__ Bl,
            int lda, int ldb, int ldc, int K,
            size_t aBatch, size_t bBatch, size_t cBatch,
            const float* __restrict__ bias, float scale,
            float* __restrict__ outF, __nv_bfloat16* __restrict__ outH,
            __nv_bfloat16* __restrict__ outL) {
    extern __shared__ char sm[];
    const uint32_t sbase = smem_u32(sm);
    const int tid = threadIdx.x;
    const int lane = tid & 31, wid = tid >> 5;
    const int wm = wid >> 2, wn = wid & 3;  // 2 x 4 warp grid
    const int z = blockIdx.z;
    Ah += (size_t)z * aBatch; Al += (size_t)z * aBatch;
    Bh += (size_t)z * bBatch; Bl += (size_t)z * bBatch;
    if (MODE == 0) { outH += (size_t)z * cBatch; outL += (size_t)z * cBatch; }
    else           { outF += (size_t)z * cBatch; }

    const int mBase = blockIdx.y * 128;
    const int nBase = blockIdx.x * 128;
    const int KT = K / BK;

    // cp.async loader for one k-tile into stage
    auto issue_load = [&](int kb, int stage) {
        const int kOff = kb * BK;
        const uint32_t sb = sbase + stage * STAGEB;
#pragma unroll
        for (int mat = 0; mat < 4; mat++) {
            const __nv_bfloat16* g = (mat == 0) ? Ah : (mat == 1) ? Al : (mat == 2) ? Bh : Bl;
            const int ld = (mat < 2) ? lda : ldb;
            const int rb = (mat < 2) ? mBase : nBase;
#pragma unroll
            for (int i = 0; i < 2; i++) {
                int idx = tid + i * 256;          // 0..511
                int r = idx >> 2, c = idx & 3;    // 128 rows x 4 x 16B
                uint32_t daddr = sb + mat * MATB + (uint32_t)(r * SST + c * 8) * 2;
                const void* gp = g + (size_t)(rb + r) * ld + kOff + c * 8;
                CP_ASYNC16(daddr, gp);
            }
        }
        CP_COMMIT();
    };

    float acc[4][4][4];
#pragma unroll
    for (int i = 0; i < 4; i++)
#pragma unroll
        for (int j = 0; j < 4; j++)
#pragma unroll
            for (int e = 0; e < 4; e++) acc[i][j][e] = 0.f;

    issue_load(0, 0);

    for (int kb = 0; kb < KT; kb++) {
        if (kb + 1 < KT) {
            issue_load(kb + 1, (kb + 1) & 1);
            asm volatile("cp.async.wait_group 1;" ::: "memory");
        } else {
            asm volatile("cp.async.wait_group 0;" ::: "memory");
        }
        __syncthreads();

        const uint32_t sb = sbase + (kb & 1) * STAGEB;
#pragma unroll
        for (int ks = 0; ks < 2; ks++) {
            // A fragments (hi & lo): 4 m-tiles
            uint32_t ah[4][4], al[4][4];
            const int rowA = wm * 64 + (lane & 15);
            const int colA = ks * 16 + (lane >> 4) * 8;
#pragma unroll
            for (int mt = 0; mt < 4; mt++) {
                uint32_t off = (uint32_t)((rowA + mt * 16) * SST + colA) * 2;
                ldm_x4(ah[mt], sb + 0 * MATB + off);
                ldm_x4(al[mt], sb + 1 * MATB + off);
            }
            // B fragments processed in pairs of n-tiles to cap live registers
            const int rB = wn * 32 + ((lane >> 4) << 3) + (lane & 7);
            const int cB = ks * 16 + (((lane >> 3) & 1) << 3);
#pragma unroll
            for (int bp = 0; bp < 2; bp++) {
                uint32_t off = (uint32_t)((rB + bp * 16) * SST + cB) * 2;
                uint32_t th[4], tl[4];
                ldm_x4(th, sb + 2 * MATB + off);
                ldm_x4(tl, sb + 3 * MATB + off);
                // product-major ordering: consecutive MMAs hit distinct accumulators
#pragma unroll
                for (int mt = 0; mt < 4; mt++) {
                    mma_bf16(acc[mt][bp * 2 + 0], ah[mt], th + 0);
                    mma_bf16(acc[mt][bp * 2 + 1], ah[mt], th + 2);
                }
#pragma unroll
                for (int mt = 0; mt < 4; mt++) {
                    mma_bf16(acc[mt][bp * 2 + 0], ah[mt], tl + 0);
                    mma_bf16(acc[mt][bp * 2 + 1], ah[mt], tl + 2);
                }
#pragma unroll
                for (int mt = 0; mt < 4; mt++) {
                    mma_bf16(acc[mt][bp * 2 + 0], al[mt], th + 0);
                    mma_bf16(acc[mt][bp * 2 + 1], al[mt], th + 2);
                }
            }
        }
        __syncthreads();
    }

    // epilogue
    const int g = lane >> 2, tq = lane & 3;
#pragma unroll
    for (int mt = 0; mt < 4; mt++) {
        const int row = mBase + wm * 64 + mt * 16 + g;
#pragma unroll
        for (int nt = 0; nt < 4; nt++) {
            const int col = nBase + wn * 32 + nt * 8 + tq * 2;
            const float* c = acc[mt][nt];
            if (MODE == 0) {
                float b0 = bias[col], b1 = bias[col + 1];
#pragma unroll
                for (int half = 0; half < 2; half++) {
                    int rr = row + half * 8;
                    float v0 = c[half * 2 + 0] + b0;
                    float v1 = c[half * 2 + 1] + b1;
                    __nv_bfloat16 h0 = __float2bfloat16(v0);
                    __nv_bfloat16 h1 = __float2bfloat16(v1);
                    __nv_bfloat16 l0 = __float2bfloat16(v0 - __bfloat162float(h0));
                    __nv_bfloat16 l1 = __float2bfloat16(v1 - __bfloat162float(h1));
                    size_t o = (size_t)rr * ldc + col;
                    *reinterpret_cast<__nv_bfloat162*>(outH + o) = __halves2bfloat162(h0, h1);
                    *reinterpret_cast<__nv_bfloat162*>(outL + o) = __halves2bfloat162(l0, l1);
                }
            } else {
                float2 v0 = {c[0] * scale, c[1] * scale};
                float2 v1 = {c[2] * scale, c[3] * scale};
                *reinterpret_cast<float2*>(outF + (size_t)row * ldc + col) = v0;
                *reinterpret_cast<float2*>(outF + (size_t)(row + 8) * ldc + col) = v1;
            }
        }
    }
}

// ---------------- launch ----------------
extern "C" void kernel_launch(void* const* d_in, const int* in_sizes, int n_in,
                              void* d_out, int out_size) {
    const float* q_in = (const float*)d_in[0];
    const float* k_in = (const float*)d_in[1];
    const float* v_in = (const float*)d_in[2];
    const float* Wq   = (const float*)d_in[3];
    const float* bq   = (const float*)d_in[4];
    const float* Wk   = (const float*)d_in[5];
    const float* bk   = (const float*)d_in[6];
    const float* Wv   = (const float*)d_in[7];
    const float* bv   = (const float*)d_in[8];
    float* out = (float*)d_out;

    cudaFuncSetAttribute(gemm_bf16x3<0>, cudaFuncAttributeMaxDynamicSharedMemorySize, SMEM_BYTES);
    cudaFuncSetAttribute(gemm_bf16x3<1>, cudaFuncAttributeMaxDynamicSharedMemorySize, SMEM_BYTES);

    void* p;
    cudaGetSymbolAddress(&p, g_xh);  __nv_bfloat16* xh = (__nv_bfloat16*)p;
    cudaGetSymbolAddress(&p, g_xl);  __nv_bfloat16* xl = (__nv_bfloat16*)p;
    cudaGetSymbolAddress(&p, g_wh);  __nv_bfloat16* wh = (__nv_bfloat16*)p;
    cudaGetSymbolAddress(&p, g_wl);  __nv_bfloat16* wl = (__nv_bfloat16*)p;
    cudaGetSymbolAddress(&p, g_qh);  __nv_bfloat16* qh = (__nv_bfloat16*)p;
    cudaGetSymbolAddress(&p, g_ql);  __nv_bfloat16* ql = (__nv_bfloat16*)p;
    cudaGetSymbolAddress(&p, g_vth); __nv_bfloat16* vth = (__nv_bfloat16*)p;
    cudaGetSymbolAddress(&p, g_vtl); __nv_bfloat16* vtl = (__nv_bfloat16*)p;
    cudaGetSymbolAddress(&p, g_S);   float* Sb = (float*)p;
    cudaGetSymbolAddress(&p, g_ph);  __nv_bfloat16* ph = (__nv_bfloat16*)p;
    cudaGetSymbolAddress(&p, g_pl);  __nv_bfloat16* pl = (__nv_bfloat16*)p;

    const float* xin[3] = {q_in, k_in, v_in};
    const float* Ws[3]  = {Wq, Wk, Wv};
    const float* bs[3]  = {bq, bk, bv};

    for (int i = 0; i < 3; i++) {
        split_f32<<<NE / (256 * 4), 256>>>(xin[i], xh + (size_t)i * NE, xl + (size_t)i * NE, NE);
        wsplit_t<<<dim3(32, 32), dim3(32, 8)>>>(Ws[i], wh + (size_t)i * WN, wl + (size_t)i * WN);
    }
    // projections: [8192,1024] = X x W + b  -> split bf16
    for (int i = 0; i < 3; i++) {
        gemm_bf16x3<0><<<dim3(8, 64, 1), 256, SMEM_BYTES>>>(
            xh + (size_t)i * NE, xl + (size_t)i * NE, wh + (size_t)i * WN, wl + (size_t)i * WN,
            1024, 1024, 1024, 1024, 0, 0, 0,
            bs[i], 0.f, nullptr, qh + (size_t)i * NE, ql + (size_t)i * NE);
    }
    // scores: per batch S[2048,2048] = Q x K^T, scale 1/32
    gemm_bf16x3<1><<<dim3(16, 16, 4), 256, SMEM_BYTES>>>(
        qh, ql, qh + NE, ql + NE,
        1024, 1024, 2048, 1024,
        (size_t)2048 * 1024, (size_t)2048 * 1024, (size_t)2048 * 2048,
        nullptr, 0.03125f, Sb, nullptr, nullptr);
    softmax_split<<<8192, 256>>>(Sb, ph, pl);
    vtrans<<<dim3(32, 64, 4), dim3(32, 8)>>>(qh + 2ull * NE, ql + 2ull * NE, vth, vtl);
    // O = P x V  (B operand = V^T rows, K-major over s)
    gemm_bf16x3<1><<<dim3(8, 16, 4), 256, SMEM_BYTES>>>(
        ph, pl, vth, vtl,
        2048, 2048, 1024, 2048,
        (size_t)2048 * 2048, (size_t)1024 * 2048, (size_t)2048 * 1024,
        nullptr, 1.0f, out, nullptr, nullptr);
}